// round 14
// baseline (speedup 1.0000x reference)
#include <cuda_runtime.h>
#include <cuda_bf16.h>
#include <math.h>

#define KK 256
#define CC 256
#define PP 196
#define OSZ 14
#define HH 112
#define WW 112
#define BB 4
#define HWSZ 12544

// conv-mma geometry (bf16, row-paired 64-bit fragments)
#define GUARD 17
#define A2STR 528                 // words per pr-row (addr64 stride 264 == 8 mod 32)
#define A2BR (8 * A2STR)          // 4224 words per branch
#define A2WORDS (2 * A2BR)        // 8448
#define B2STR 144                 // words per pr-row (addr64 stride 72 == 8 mod 32)
#define B2BUF (8 * B2STR)         // 1152 words per buffer
#define B2WORDS (2 * B2BUF)       // 2304
#define RAWF 6272                 // 196*32 floats per branch
#define CONV_SMEM ((A2WORDS + B2WORDS + 2 * RAWF) * 4)    // 93184 B
#define OUT2_STR 233

// gcn2-mma geometry
#define G2_ASTR 232
#define G2_XSTR 72

// aff-mma geometry
#define AFF_ASTR 232
#define AFF_WSTR 72
#define AFF_SMEM ((64 * AFF_ASTR + 64 * AFF_WSTR) * 4)

// ---------------- scratch ----------------
__device__ float g_semT[BB * HWSZ * CC];
__device__ float g_roisem[KK * PP * CC];
__device__ float g_abuf[KK * 64 * PP];
__device__ float g_Abuf[KK * PP * PP];
__device__ float g_deg[KK * PP];
__device__ float g_xw2[KK * PP * CC];
__device__ unsigned g_wsemP[128 * 9 * 64];
__device__ unsigned g_wfpnP[128 * 9 * 64];
__device__ float g_waffT[64 * PP];
__device__ int   g_tapoff[KK * PP * 9];
__device__ float g_tapw[KK * PP * 9];
__device__ float g_sc_sem[CC], g_sh_sem[CC];
__device__ float g_sc_fpn[CC], g_sh_fpn[CC];
__device__ float g_sc_aff[64], g_sh_aff[64];

__device__ __forceinline__ float cvt_tf32(float x) {
    unsigned r;
    asm("cvt.rna.tf32.f32 %0, %1;" : "=r"(r) : "f"(x));
    return __uint_as_float(r);
}

__device__ __forceinline__ unsigned pack_bf2(float a, float b) {
    __nv_bfloat162 h = __floats2bfloat162_rn(a, b);
    return *(unsigned*)&h;
}

__device__ __forceinline__ void cp_async16(float* smem_dst, const float* gsrc) {
    unsigned saddr = (unsigned)__cvta_generic_to_shared(smem_dst);
    asm volatile("cp.async.cg.shared.global [%0], [%1], 16;" :: "r"(saddr), "l"(gsrc));
}

__device__ __forceinline__ void mma_tf32(float* c, const unsigned* a, const unsigned* b) {
    asm volatile(
        "mma.sync.aligned.m16n8k8.row.col.f32.tf32.tf32.f32 "
        "{%0,%1,%2,%3}, {%4,%5,%6,%7}, {%8,%9}, {%0,%1,%2,%3};"
        : "+f"(c[0]), "+f"(c[1]), "+f"(c[2]), "+f"(c[3])
        : "r"(a[0]), "r"(a[1]), "r"(a[2]), "r"(a[3]), "r"(b[0]), "r"(b[1]));
}

__device__ __forceinline__ void mma_bf16(float* c, const unsigned* a, const unsigned* b) {
    asm volatile(
        "mma.sync.aligned.m16n8k16.row.col.f32.bf16.bf16.f32 "
        "{%0,%1,%2,%3}, {%4,%5,%6,%7}, {%8,%9}, {%0,%1,%2,%3};"
        : "+f"(c[0]), "+f"(c[1]), "+f"(c[2]), "+f"(c[3])
        : "r"(a[0]), "r"(a[1]), "r"(a[2]), "r"(a[3]), "r"(b[0]), "r"(b[1]));
}

// ---------------- merged prep + semantic transpose ----------------
#define TRANS_BASE (KK + 1 + 128)
__global__ void k_prep_trans(const float* __restrict__ boxes,
                             const float* gs, const float* bs, const float* ms, const float* vs,
                             const float* gf, const float* bfn, const float* mf, const float* vf,
                             const float* ga, const float* ba, const float* ma, const float* va,
                             const float* wsem, const float* wfpn, const float* waff,
                             const float* __restrict__ sem) {
    int bid = blockIdx.x;
    int tid = threadIdx.x;
    if (bid < KK) {
        int k = bid;
        int p = tid;
        if (p >= PP) return;
        g_deg[k * PP + p] = 0.f;
        int bidx = (int)boxes[k * 5 + 0];
        float x1 = boxes[k * 5 + 1], y1 = boxes[k * 5 + 2];
        int oy = p / OSZ, ox = p % OSZ;
        int base = bidx * HWSZ * CC;
        int r0 = (int)floorf(y1 + 0.5f);
        int c0 = (int)floorf(x1 + 0.5f);
        float ly = (y1 + 0.5f) - (float)r0;
        float lx = (x1 + 0.5f) - (float)c0;
        float wy[3] = {0.5f * (1.f - ly), 0.5f, 0.5f * ly};
        float wx[3] = {0.5f * (1.f - lx), 0.5f, 0.5f * lx};
        int ry[3], cx[3];
#pragma unroll
        for (int d = 0; d < 3; d++) {
            ry[d] = min(r0 + 2 * oy + d, HH - 1);
            cx[d] = min(c0 + 2 * ox + d, WW - 1);
        }
        int* toff = g_tapoff + ((size_t)k * PP + p) * 9;
        float* tw = g_tapw + ((size_t)k * PP + p) * 9;
#pragma unroll
        for (int dy = 0; dy < 3; dy++)
#pragma unroll
            for (int dx = 0; dx < 3; dx++) {
                toff[dy * 3 + dx] = base + (ry[dy] * WW + cx[dx]) * CC;
                tw[dy * 3 + dx] = wy[dy] * wx[dx];
            }
    } else if (bid == KK) {
        int t = tid;
        if (t < CC) {
            float s = gs[t] * rsqrtf(vs[t] + 1e-5f);
            g_sc_sem[t] = s;
            g_sh_sem[t] = bs[t] - ms[t] * s;
            float f = gf[t] * rsqrtf(vf[t] + 1e-5f);
            g_sc_fpn[t] = f;
            g_sh_fpn[t] = bfn[t] - mf[t] * f;
        }
        if (t < 64) {
            float a = ga[t] * rsqrtf(va[t] + 1e-5f);
            g_sc_aff[t] = a;
            g_sh_aff[t] = ba[t] - ma[t] * a;
        }
    } else if (bid < TRANS_BASE) {
        const int NW = 128 * 9 * 64;
        const int NA = 64 * PP;
        int total = 2 * NW + NA;
        int stride = 128 * 256;
        for (int d = (bid - KK - 1) * 256 + tid; d < total; d += stride) {
            if (d < NW) {
                int cp = d / 576, r = d % 576, tap = r / 64, oc = r % 64;
                g_wsemP[d] = pack_bf2(wsem[oc * (CC * 9) + (2 * cp) * 9 + tap],
                                      wsem[oc * (CC * 9) + (2 * cp + 1) * 9 + tap]);
            } else if (d < 2 * NW) {
                int e = d - NW;
                int cp = e / 576, r = e % 576, tap = r / 64, oc = r % 64;
                g_wfpnP[e] = pack_bf2(wfpn[oc * (CC * 9) + (2 * cp) * 9 + tap],
                                      wfpn[oc * (CC * 9) + (2 * cp + 1) * 9 + tap]);
            } else {
                int e = d - 2 * NW;
                int c = e / PP, n = e % PP;
                g_waffT[e] = waff[n * 64 + c];
            }
        }
    } else {
        // semantic transpose NCHW -> NHWC
        __shared__ float tile[32][33];
        int bid2 = bid - TRANS_BASE;
        int b = bid2 / (392 * 8);
        int rem = bid2 % (392 * 8);
        int c0 = (rem / 392) * 32;
        int hw0 = (rem % 392) * 32;
        int tx = tid & 31, ty = tid >> 5;
        const float* src = sem + (size_t)b * CC * HWSZ;
        float* dst = g_semT + (size_t)b * HWSZ * CC;
#pragma unroll
        for (int yy = 0; yy < 32; yy += 8)
            tile[ty + yy][tx] = src[(size_t)(c0 + ty + yy) * HWSZ + hw0 + tx];
        __syncthreads();
#pragma unroll
        for (int yy = 0; yy < 32; yy += 8)
            dst[(size_t)(hw0 + ty + yy) * CC + c0 + tx] = tile[tx][ty + yy];
    }
}

// ---------------- ROI align gather (9-tap) ----------------
__global__ __launch_bounds__(256)
void k_roialign() {
    __shared__ int soff[28 * 9];
    __shared__ float sw[28 * 9];
    int k = blockIdx.y;
    int p0 = blockIdx.x * 28;
    int tid = threadIdx.x;
    for (int i = tid; i < 28 * 9; i += 256) {
        soff[i] = g_tapoff[((size_t)k * PP + p0) * 9 + i];
        sw[i] = g_tapw[((size_t)k * PP + p0) * 9 + i];
    }
    __syncthreads();
    int c = tid;
    for (int pp = 0; pp < 28; pp++) {
        float acc = 0.f;
#pragma unroll
        for (int t = 0; t < 9; t++)
            acc += sw[pp * 9 + t] * __ldg(&g_semT[soff[pp * 9 + t] + c]);
        g_roisem[((size_t)k * PP + p0 + pp) * CC + c] = acc;
    }
}

// ---------------- bf16 conv: cp.async staging + row-paired 64-bit fragments ----------------
// act2[br][pr][pos][half]: pr = s*4 + rr%4, half = rr/4 for cp-row rr (pairs r, r+4).
// B2[buf][pr][oc][half]: same pairing.
__global__ __launch_bounds__(256, 2)
void k_conv_mma(const float* __restrict__ roi_feature,
                const float* __restrict__ bias_sem, const float* __restrict__ bias_fpn) {
    extern __shared__ float dyn[];
    unsigned* act2 = (unsigned*)dyn;
    unsigned* B2 = act2 + A2WORDS;
    float* rawS = (float*)(act2 + A2WORDS + B2WORDS);
    float* rawF = rawS + RAWF;
    int k = blockIdx.x;
    int tid = threadIdx.x;
    int warp = tid >> 5;
    int lane = tid & 31;
    int g = lane >> 2;
    int t = lane & 3;
    int wrow = warp * 32;

    float acc[2][8][4];
#pragma unroll
    for (int mg = 0; mg < 2; mg++)
#pragma unroll
        for (int n8 = 0; n8 < 8; n8++)
#pragma unroll
            for (int q = 0; q < 4; q++) acc[mg][n8][q] = 0.f;

    const float* rfk = roi_feature + (size_t)k * CC * PP;
    const float* rsk = g_roisem + (size_t)k * PP * CC;

    for (int i = tid; i < A2WORDS; i += 256) act2[i] = 0u;

    // fetch chunk0 raw via cp.async
    for (int i = tid; i < PP * 8; i += 256) {
        int p = i >> 3, seg = i & 7;
        cp_async16(rawS + p * 32 + seg * 4, rsk + (size_t)p * CC + seg * 4);
    }
    for (int i = tid; i < 32 * 49; i += 256) {
        int row = i / 49, seg = i % 49;
        cp_async16(rawF + row * PP + seg * 4, rfk + (size_t)row * PP + seg * 4);
    }
    asm volatile("cp.async.commit_group;");
    asm volatile("cp.async.wait_group 0;");
    __syncthreads();
    // convert chunk0 raw -> act2
    for (int i = tid; i < PP * 16; i += 256) {
        int p = i >> 4, cp = i & 15;
        int c = 2 * cp;
        int s = cp >> 3, rr = cp & 7;
        int pr = s * 4 + (rr & 3), half = rr >> 2;
        float v0 = fmaxf(rawS[p * 32 + c] * g_sc_sem[c] + g_sh_sem[c], 0.f);
        float v1 = fmaxf(rawS[p * 32 + c + 1] * g_sc_sem[c + 1] + g_sh_sem[c + 1], 0.f);
        int pos = GUARD + (p / OSZ) * 16 + (p % OSZ);
        act2[pr * A2STR + pos * 2 + half] = pack_bf2(v0, v1);
    }
    for (int i = tid; i < 16 * PP; i += 256) {
        int cp = i / PP, p = i % PP;
        int c = 2 * cp;
        int s = cp >> 3, rr = cp & 7;
        int pr = s * 4 + (rr & 3), half = rr >> 2;
        float v0 = fmaxf(rawF[(2 * cp) * PP + p] * g_sc_fpn[c] + g_sh_fpn[c], 0.f);
        float v1 = fmaxf(rawF[(2 * cp + 1) * PP + p] * g_sc_fpn[c + 1] + g_sh_fpn[c + 1], 0.f);
        int pos = GUARD + (p / OSZ) * 16 + (p % OSZ);
        act2[A2BR + pr * A2STR + pos * 2 + half] = pack_bf2(v0, v1);
    }

    for (int chunk = 0; chunk < 8; chunk++) {
        int ic0 = chunk * 32;
        int icp0 = ic0 >> 1;
        // stage B tap0 into buf 0
#pragma unroll
        for (int j = 0; j < 4; j++) {
            int id2 = tid + j * 256;
            int cp = id2 >> 6, oc = id2 & 63;
            int s = cp >> 3, rr = cp & 7;
            int pr = s * 4 + (rr & 3), half = rr >> 2;
            B2[pr * B2STR + oc * 2 + half] = g_wsemP[(size_t)(icp0 + cp) * 576 + 0 * 64 + oc];
        }
        if (chunk < 7) {
            int nic0 = ic0 + 32;
            for (int i = tid; i < PP * 8; i += 256) {
                int p = i >> 3, seg = i & 7;
                cp_async16(rawS + p * 32 + seg * 4, rsk + (size_t)p * CC + nic0 + seg * 4);
            }
            for (int i = tid; i < 32 * 49; i += 256) {
                int row = i / 49, seg = i % 49;
                cp_async16(rawF + row * PP + seg * 4, rfk + (size_t)(nic0 + row) * PP + seg * 4);
            }
            asm volatile("cp.async.commit_group;");
        }
        __syncthreads();

        int cur = 0;
        for (int idx = 0; idx < 18; idx++) {
            int br = idx / 9, tap = idx % 9;
            int off = (tap / 3 - 1) * 16 + (tap % 3 - 1);
            unsigned pw[4];
            if (idx < 17) {
                int nbr = (idx + 1) / 9, ntap = (idx + 1) % 9;
                const unsigned* wP = nbr ? g_wfpnP : g_wsemP;
#pragma unroll
                for (int j = 0; j < 4; j++) {
                    int id2 = tid + j * 256;
                    int cp = id2 >> 6, oc = id2 & 63;
                    pw[j] = wP[(size_t)(icp0 + cp) * 576 + ntap * 64 + oc];
                }
            }
            if (warp < 7) {
                const unsigned* actb = act2 + br * A2BR;
                const unsigned* Bc = B2 + cur * B2BUF;
#pragma unroll
                for (int s = 0; s < 2; s++) {
                    int pr = s * 4 + t;
                    unsigned bf[8][2];
#pragma unroll
                    for (int n8 = 0; n8 < 8; n8++) {
                        uint2 v = *(const uint2*)(Bc + pr * B2STR + (n8 * 8 + g) * 2);
                        bf[n8][0] = v.x;
                        bf[n8][1] = v.y;
                    }
                    unsigned af[2][4];
#pragma unroll
                    for (int mg = 0; mg < 2; mg++) {
                        int pos = GUARD + wrow + mg * 16 + g + off;
                        uint2 v0 = *(const uint2*)(actb + pr * A2STR + pos * 2);
                        uint2 v1 = *(const uint2*)(actb + pr * A2STR + (pos + 8) * 2);
                        af[mg][0] = v0.x;
                        af[mg][1] = v1.x;
                        af[mg][2] = v0.y;
                        af[mg][3] = v1.y;
                    }
#pragma unroll
                    for (int mg = 0; mg < 2; mg++)
#pragma unroll
                        for (int n8 = 0; n8 < 8; n8++)
                            mma_bf16(acc[mg][n8], af[mg], bf[n8]);
                }
            }
            if (idx < 17) {
                unsigned* d = B2 + (cur ^ 1) * B2BUF;
#pragma unroll
                for (int j = 0; j < 4; j++) {
                    int id2 = tid + j * 256;
                    int cp = id2 >> 6, oc = id2 & 63;
                    int s = cp >> 3, rr = cp & 7;
                    int pr = s * 4 + (rr & 3), half = rr >> 2;
                    d[pr * B2STR + oc * 2 + half] = pw[j];
                }
            }
            __syncthreads();
            cur ^= 1;
        }

        if (chunk < 7) {
            int nic0 = ic0 + 32;
            asm volatile("cp.async.wait_group 0;");
            __syncthreads();
            for (int i = tid; i < PP * 16; i += 256) {
                int p = i >> 4, cp = i & 15;
                int c = nic0 + 2 * cp;
                int s = cp >> 3, rr = cp & 7;
                int pr = s * 4 + (rr & 3), half = rr >> 2;
                float v0 = fmaxf(rawS[p * 32 + 2 * cp] * g_sc_sem[c] + g_sh_sem[c], 0.f);
                float v1 = fmaxf(rawS[p * 32 + 2 * cp + 1] * g_sc_sem[c + 1] + g_sh_sem[c + 1], 0.f);
                int pos = GUARD + (p / OSZ) * 16 + (p % OSZ);
                act2[pr * A2STR + pos * 2 + half] = pack_bf2(v0, v1);
            }
            for (int i = tid; i < 16 * PP; i += 256) {
                int cp = i / PP, p = i % PP;
                int c = nic0 + 2 * cp;
                int s = cp >> 3, rr = cp & 7;
                int pr = s * 4 + (rr & 3), half = rr >> 2;
                float v0 = fmaxf(rawF[(2 * cp) * PP + p] * g_sc_fpn[c] + g_sh_fpn[c], 0.f);
                float v1 = fmaxf(rawF[(2 * cp + 1) * PP + p] * g_sc_fpn[c + 1] + g_sh_fpn[c + 1], 0.f);
                int pos = GUARD + (p / OSZ) * 16 + (p % OSZ);
                act2[A2BR + pr * A2STR + pos * 2 + half] = pack_bf2(v0, v1);
            }
        }
    }

    // epilogue: two 32-oc passes through smem
    float* outsm = dyn;
#pragma unroll
    for (int og = 0; og < 2; og++) {
        __syncthreads();
        if (warp < 7) {
#pragma unroll
            for (int mg = 0; mg < 2; mg++) {
                int r0 = wrow + mg * 16 + g;
#pragma unroll
                for (int nn = 0; nn < 4; nn++) {
                    int n8 = og * 4 + nn;
                    int ocl = nn * 8 + 2 * t;
                    outsm[ocl * OUT2_STR + r0] = acc[mg][n8][0];
                    outsm[(ocl + 1) * OUT2_STR + r0] = acc[mg][n8][1];
                    outsm[ocl * OUT2_STR + r0 + 8] = acc[mg][n8][2];
                    outsm[(ocl + 1) * OUT2_STR + r0 + 8] = acc[mg][n8][3];
                }
            }
        }
        __syncthreads();
        for (int i = tid; i < 32 * PP; i += 256) {
            int ocl = i / PP, p = i % PP;
            int oc = og * 32 + ocl;
            float v = outsm[ocl * OUT2_STR + (p / OSZ) * 16 + (p % OSZ)];
            g_abuf[((size_t)k * 64 + oc) * PP + p] = v + __ldg(&bias_sem[oc]) + __ldg(&bias_fpn[oc]);
        }
    }
}

// ---------------- aff via tf32 mma + sigmoid + deg ----------------
__global__ __launch_bounds__(224)
void k_aff_mma(const float* __restrict__ aff_b) {
    extern __shared__ float dyn[];
    float* sA = dyn;
    float* sW = dyn + 64 * AFF_ASTR;
    int n0 = blockIdx.x * 56;
    int k = blockIdx.y;
    int tid = threadIdx.x;
    int warp = tid >> 5;
    int lane = tid & 31;
    int g = lane >> 2;
    int t = lane & 3;
    int wrow = warp * 32;

    for (int idx = tid; idx < 64 * 224; idx += 224) {
        int c = idx / 224, p = idx % 224;
        float v = 0.f;
        if (p < PP) {
            float a = g_abuf[((size_t)k * 64 + c) * PP + p];
            v = fmaxf(a * g_sc_aff[c] + g_sh_aff[c], 0.f);
        }
        sA[c * AFF_ASTR + p] = cvt_tf32(v);
    }
    for (int idx = tid; idx < 64 * 56; idx += 224) {
        int c = idx / 56, nn = idx % 56;
        int n = n0 + nn;
        float v = (n < PP) ? g_waffT[c * PP + n] : 0.f;
        sW[c * AFF_WSTR + nn] = cvt_tf32(v);
    }
    __syncthreads();

    float acc[2][7][4];
#pragma unroll
    for (int mg = 0; mg < 2; mg++)
#pragma unroll
        for (int n8 = 0; n8 < 7; n8++)
#pragma unroll
            for (int q = 0; q < 4; q++) acc[mg][n8][q] = 0.f;

#pragma unroll
    for (int ks = 0; ks < 8; ks++) {
        unsigned bf[7][2];
#pragma unroll
        for (int n8 = 0; n8 < 7; n8++) {
            bf[n8][0] = __float_as_uint(sW[(ks * 8 + t) * AFF_WSTR + n8 * 8 + g]);
            bf[n8][1] = __float_as_uint(sW[(ks * 8 + t + 4) * AFF_WSTR + n8 * 8 + g]);
        }
        unsigned af[2][4];
#pragma unroll
        for (int mg = 0; mg < 2; mg++) {
            int r0 = wrow + mg * 16 + g;
            const float* a0 = sA + (ks * 8 + t) * AFF_ASTR + r0;
            const float* a1 = sA + (ks * 8 + t + 4) * AFF_ASTR + r0;
            af[mg][0] = __float_as_uint(a0[0]);
            af[mg][1] = __float_as_uint(a0[8]);
            af[mg][2] = __float_as_uint(a1[0]);
            af[mg][3] = __float_as_uint(a1[8]);
        }
#pragma unroll
        for (int mg = 0; mg < 2; mg++)
#pragma unroll
            for (int n8 = 0; n8 < 7; n8++)
                mma_tf32(acc[mg][n8], af[mg], bf[n8]);
    }

    float* Ak = g_Abuf + (size_t)k * PP * PP;
#pragma unroll
    for (int mg = 0; mg < 2; mg++) {
#pragma unroll
        for (int half = 0; half < 2; half++) {
            int p = wrow + mg * 16 + g + half * 8;
            if (p < PP) {
                float dpart = 0.f;
#pragma unroll
                for (int n8 = 0; n8 < 7; n8++) {
#pragma unroll
                    for (int q = 0; q < 2; q++) {
                        int n = n0 + n8 * 8 + 2 * t + q;
                        if (n < PP) {
                            float v = acc[mg][n8][half * 2 + q] + __ldg(&aff_b[n]);
                            float s = 1.f / (1.f + expf(-v));
                            Ak[(size_t)n * PP + p] = s;
                            dpart += s;
                        }
                    }
                }
                atomicAdd(&g_deg[k * PP + p], dpart);
            }
        }
    }
}

// ---------------- fused xw1 + agg1 + relu + (x1 @ w2) scaled ----------------
__global__ __launch_bounds__(224)
void k_gcn1f(const float* __restrict__ rf, const float* __restrict__ w1,
             const float* __restrict__ b1, const float* __restrict__ w2) {
    __shared__ __align__(16) float sW1[CC * 16];
    __shared__ __align__(16) float sXW[PP * 16];
    __shared__ __align__(16) float sW2[16 * CC];
    int k = blockIdx.x;
    int tid = threadIdx.x;
    for (int i = tid; i < CC * 16; i += 224) sW1[i] = w1[i];
    for (int i = tid; i < 16 * CC; i += 224) sW2[i] = w2[i];
    __syncthreads();

    {
        int i = tid;
        if (i < PP) {
            float acc[16];
#pragma unroll
            for (int f = 0; f < 16; f++) acc[f] = 0.f;
            const float* x = rf + (size_t)k * CC * PP;
            for (int c = 0; c < CC; c++) {
                float v = x[c * PP + i];
#pragma unroll
                for (int fg = 0; fg < 4; fg++) {
                    float4 w4 = *(const float4*)&sW1[c * 16 + fg * 4];
                    acc[fg * 4 + 0] += v * w4.x;
                    acc[fg * 4 + 1] += v * w4.y;
                    acc[fg * 4 + 2] += v * w4.z;
                    acc[fg * 4 + 3] += v * w4.w;
                }
            }
            float di = rsqrtf(g_deg[k * PP + i]);
#pragma unroll
            for (int f = 0; f < 16; f++) sXW[i * 16 + f] = di * acc[f];
        }
    }
    __syncthreads();

    int j = tid;
    if (j >= PP) return;
    float acc[16];
#pragma unroll
    for (int f = 0; f < 16; f++) acc[f] = 0.f;
    const float* A = g_Abuf + (size_t)k * PP * PP;
    for (int i = 0; i < PP; i++) {
        float a = A[i * PP + j];
#pragma unroll
        for (int fg = 0; fg < 4; fg++) {
            float4 xv = *(const float4*)&sXW[i * 16 + fg * 4];
            acc[fg * 4 + 0] += a * xv.x;
            acc[fg * 4 + 1] += a * xv.y;
            acc[fg * 4 + 2] += a * xv.z;
            acc[fg * 4 + 3] += a * xv.w;
        }
    }
    float dj = rsqrtf(g_deg[k * PP + j]);
    float x1[16];
#pragma unroll
    for (int f = 0; f < 16; f++) x1[f] = fmaxf(acc[f] * dj + b1[f], 0.f);
    float* o = g_xw2 + ((size_t)k * PP + j) * CC;
    for (int g = 0; g < 64; g++) {
        float4 s = make_float4(0.f, 0.f, 0.f, 0.f);
#pragma unroll
        for (int f = 0; f < 16; f++) {
            float4 w4 = *(const float4*)&sW2[f * CC + g * 4];
            s.x += x1[f] * w4.x;
            s.y += x1[f] * w4.y;
            s.z += x1[f] * w4.z;
            s.w += x1[f] * w4.w;
        }
        s.x *= dj; s.y *= dj; s.z *= dj; s.w *= dj;
        *(float4*)&o[g * 4] = s;
    }
}

// ---------------- agg2 via tf32 mma ----------------
__global__ __launch_bounds__(224)
void k_gcn2_mma(const float* __restrict__ b2, float* __restrict__ out) {
    __shared__ float sA[32 * G2_ASTR];
    __shared__ float sX[32 * G2_XSTR];
    int f0 = blockIdx.x * 64;
    int k = blockIdx.y;
    int tid = threadIdx.x;
    int warp = tid >> 5;
    int lane = tid & 31;
    int g = lane >> 2;
    int t = lane & 3;
    int wrow = warp * 32;

    float acc[2][8][4];
#pragma unroll
    for (int mg = 0; mg < 2; mg++)
#pragma unroll
        for (int n8 = 0; n8 < 8; n8++)
#pragma unroll
            for (int q = 0; q < 4; q++) acc[mg][n8][q] = 0.f;

    const float* A = g_Abuf + (size_t)k * PP * PP;
    const float* X2 = g_xw2 + (size_t)k * PP * CC;

    for (int i0 = 0; i0 < 224; i0 += 32) {
        __syncthreads();
        for (int ii = 0; ii < 32; ii++) {
            int i = i0 + ii;
            float v = (i < PP && tid < PP) ? A[(size_t)i * PP + tid] : 0.f;
            sA[ii * G2_ASTR + tid] = cvt_tf32(v);
        }
        for (int idx = tid; idx < 32 * 64; idx += 224) {
            int ii = idx >> 6, ff = idx & 63;
            int i = i0 + ii;
            float v = (i < PP) ? X2[(size_t)i * CC + f0 + ff] : 0.f;
            sX[ii * G2_XSTR + ff] = cvt_tf32(v);
        }
        __syncthreads();
#pragma unroll
        for (int ks = 0; ks < 4; ks++) {
            unsigned bf[8][2];
#pragma unroll
            for (int n8 = 0; n8 < 8; n8++) {
                bf[n8][0] = __float_as_uint(sX[(ks * 8 + t) * G2_XSTR + n8 * 8 + g]);
                bf[n8][1] = __float_as_uint(sX[(ks * 8 + t + 4) * G2_XSTR + n8 * 8 + g]);
            }
            unsigned af[2][4];
#pragma unroll
            for (int mg = 0; mg < 2; mg++) {
                int r0 = wrow + mg * 16 + g;
                const float* a0 = sA + (ks * 8 + t) * G2_ASTR + r0;
                const float* a1 = sA + (ks * 8 + t + 4) * G2_ASTR + r0;
                af[mg][0] = __float_as_uint(a0[0]);
                af[mg][1] = __float_as_uint(a0[8]);
                af[mg][2] = __float_as_uint(a1[0]);
                af[mg][3] = __float_as_uint(a1[8]);
            }
#pragma unroll
            for (int mg = 0; mg < 2; mg++)
#pragma unroll
                for (int n8 = 0; n8 < 8; n8++)
                    mma_tf32(acc[mg][n8], af[mg], bf[n8]);
        }
    }

#pragma unroll
    for (int mg = 0; mg < 2; mg++) {
#pragma unroll
        for (int half = 0; half < 2; half++) {
            int j = wrow + mg * 16 + g + half * 8;
            if (j < PP) {
                float dj = rsqrtf(g_deg[k * PP + j]);
                const float* rs = g_roisem + ((size_t)k * PP + j) * CC;
#pragma unroll
                for (int n8 = 0; n8 < 8; n8++) {
                    int f = f0 + n8 * 8 + 2 * t;
                    float v0 = acc[mg][n8][half * 2 + 0];
                    float v1 = acc[mg][n8][half * 2 + 1];
                    out[((size_t)k * CC + f) * PP + j] = rs[f] + dj * v0 + __ldg(&b2[f]);
                    out[((size_t)k * CC + f + 1) * PP + j] = rs[f + 1] + dj * v1 + __ldg(&b2[f + 1]);
                }
            }
        }
    }
}

// ---------------- launch ----------------
extern "C" void kernel_launch(void* const* d_in, const int* in_sizes, int n_in,
                              void* d_out, int out_size) {
    const float* roi_feature = (const float*)d_in[0];
    const float* semantic = (const float*)d_in[1];
    const float* boxes = (const float*)d_in[2];
    const float* bn_sem_g = (const float*)d_in[3];
    const float* bn_sem_b = (const float*)d_in[4];
    const float* bn_sem_m = (const float*)d_in[5];
    const float* bn_sem_v = (const float*)d_in[6];
    const float* conv_sem_w = (const float*)d_in[7];
    const float* conv_sem_b = (const float*)d_in[8];
    const float* bn_fpn_g = (const float*)d_in[9];
    const float* bn_fpn_b = (const float*)d_in[10];
    const float* bn_fpn_m = (const float*)d_in[11];
    const float* bn_fpn_v = (const float*)d_in[12];
    const float* conv_fpn_w = (const float*)d_in[13];
    const float* conv_fpn_b = (const float*)d_in[14];
    const float* bn_aff_g = (const float*)d_in[15];
    const float* bn_aff_b = (const float*)d_in[16];
    const float* bn_aff_m = (const float*)d_in[17];
    const float* bn_aff_v = (const float*)d_in[18];
    const float* conv_aff_w = (const float*)d_in[19];
    const float* conv_aff_b = (const float*)d_in[20];
    const float* gcn1_w = (const float*)d_in[21];
    const float* gcn1_b = (const float*)d_in[22];
    const float* gcn2_w = (const float*)d_in[23];
    const float* gcn2_b = (const float*)d_in[24];
    float* out = (float*)d_out;

    static int smem_set = 0;
    if (!smem_set) {
        cudaFuncSetAttribute(k_conv_mma, cudaFuncAttributeMaxDynamicSharedMemorySize, CONV_SMEM);
        cudaFuncSetAttribute(k_aff_mma, cudaFuncAttributeMaxDynamicSharedMemorySize, AFF_SMEM);
        smem_set = 1;
    }

    k_prep_trans<<<TRANS_BASE + 12544, 256>>>(boxes,
                                              bn_sem_g, bn_sem_b, bn_sem_m, bn_sem_v,
                                              bn_fpn_g, bn_fpn_b, bn_fpn_m, bn_fpn_v,
                                              bn_aff_g, bn_aff_b, bn_aff_m, bn_aff_v,
                                              conv_sem_w, conv_fpn_w, conv_aff_w, semantic);
    {
        dim3 g(7, KK);
        k_roialign<<<g, 256>>>();
    }
    k_conv_mma<<<KK, 256, CONV_SMEM>>>(roi_feature, conv_sem_b, conv_fpn_b);
    {
        dim3 g(4, KK);
        k_aff_mma<<<g, 224, AFF_SMEM>>>(conv_aff_b);
    }
    k_gcn1f<<<KK, 224>>>(roi_feature, gcn1_w, gcn1_b, gcn2_w);
    {
        dim3 g(4, KK);
        k_gcn2_mma<<<g, 224>>>(gcn2_b, out);
    }
}

// round 16
// speedup vs baseline: 1.0970x; 1.0970x over previous
#include <cuda_runtime.h>
#include <cuda_bf16.h>
#include <math.h>

#define KK 256
#define CC 256
#define PP 196
#define OSZ 14
#define HH 112
#define WW 112
#define BB 4
#define HWSZ 12544

// conv-mma geometry (bf16 + cp.async raw staging) — R13 proven
#define ACT_STRW 296
#define GUARD 17
#define BWSTR 72
#define ACT_WORDS (32 * ACT_STRW)
#define B_WORDS (2 * 16 * BWSTR)
#define RAWF 6272
#define CONV_SMEM ((ACT_WORDS + B_WORDS + 2 * RAWF) * 4)
#define OUT2_STR 233

// gcn2-mma geometry
#define G2_ASTR 232
#define G2_XSTR 72

// aff-mma geometry
#define AFF_ASTR 232
#define AFF_WSTR 72
#define AFF_SMEM ((64 * AFF_ASTR + 64 * AFF_WSTR) * 4)

// ---------------- scratch ----------------
__device__ float g_semT[BB * HWSZ * CC];
__device__ float g_roisem[KK * PP * CC];
__device__ float g_abuf[KK * 64 * PP];
__device__ float g_Abuf[KK * PP * PP];
__device__ float g_deg[KK * PP];
__device__ float g_xw2[KK * PP * CC];
__device__ unsigned g_wsemP[128 * 9 * 64];
__device__ unsigned g_wfpnP[128 * 9 * 64];
__device__ float g_waffT[64 * PP];
__device__ int   g_tapoff[KK * PP * 9];
__device__ float g_tapw[KK * PP * 9];
__device__ float g_sc_sem[CC], g_sh_sem[CC];
__device__ float g_sc_fpn[CC], g_sh_fpn[CC];
__device__ float g_sc_aff[64], g_sh_aff[64];

__device__ __forceinline__ float cvt_tf32(float x) {
    unsigned r;
    asm("cvt.rna.tf32.f32 %0, %1;" : "=r"(r) : "f"(x));
    return __uint_as_float(r);
}

__device__ __forceinline__ unsigned pack_bf2(float a, float b) {
    __nv_bfloat162 h = __floats2bfloat162_rn(a, b);
    return *(unsigned*)&h;
}

__device__ __forceinline__ void cp_async16(float* smem_dst, const float* gsrc) {
    unsigned saddr = (unsigned)__cvta_generic_to_shared(smem_dst);
    asm volatile("cp.async.cg.shared.global [%0], [%1], 16;" :: "r"(saddr), "l"(gsrc));
}

__device__ __forceinline__ void mma_tf32(float* c, const unsigned* a, const unsigned* b) {
    asm volatile(
        "mma.sync.aligned.m16n8k8.row.col.f32.tf32.tf32.f32 "
        "{%0,%1,%2,%3}, {%4,%5,%6,%7}, {%8,%9}, {%0,%1,%2,%3};"
        : "+f"(c[0]), "+f"(c[1]), "+f"(c[2]), "+f"(c[3])
        : "r"(a[0]), "r"(a[1]), "r"(a[2]), "r"(a[3]), "r"(b[0]), "r"(b[1]));
}

__device__ __forceinline__ void mma_bf16(float* c, const unsigned* a, const unsigned* b) {
    asm volatile(
        "mma.sync.aligned.m16n8k16.row.col.f32.bf16.bf16.f32 "
        "{%0,%1,%2,%3}, {%4,%5,%6,%7}, {%8,%9}, {%0,%1,%2,%3};"
        : "+f"(c[0]), "+f"(c[1]), "+f"(c[2]), "+f"(c[3])
        : "r"(a[0]), "r"(a[1]), "r"(a[2]), "r"(a[3]), "r"(b[0]), "r"(b[1]));
}

// ---------------- merged prep + semantic transpose ----------------
#define TRANS_BASE (KK + 1 + 128)
__global__ void k_prep_trans(const float* __restrict__ boxes,
                             const float* gs, const float* bs, const float* ms, const float* vs,
                             const float* gf, const float* bfn, const float* mf, const float* vf,
                             const float* ga, const float* ba, const float* ma, const float* va,
                             const float* wsem, const float* wfpn, const float* waff,
                             const float* __restrict__ sem) {
    int bid = blockIdx.x;
    int tid = threadIdx.x;
    if (bid < KK) {
        int k = bid;
        int p = tid;
        if (p >= PP) return;
        int bidx = (int)boxes[k * 5 + 0];
        float x1 = boxes[k * 5 + 1], y1 = boxes[k * 5 + 2];
        int oy = p / OSZ, ox = p % OSZ;
        int base = bidx * HWSZ * CC;
        int r0 = (int)floorf(y1 + 0.5f);
        int c0 = (int)floorf(x1 + 0.5f);
        float ly = (y1 + 0.5f) - (float)r0;
        float lx = (x1 + 0.5f) - (float)c0;
        float wy[3] = {0.5f * (1.f - ly), 0.5f, 0.5f * ly};
        float wx[3] = {0.5f * (1.f - lx), 0.5f, 0.5f * lx};
        int ry[3], cx[3];
#pragma unroll
        for (int d = 0; d < 3; d++) {
            ry[d] = min(r0 + 2 * oy + d, HH - 1);
            cx[d] = min(c0 + 2 * ox + d, WW - 1);
        }
        int* toff = g_tapoff + ((size_t)k * PP + p) * 9;
        float* tw = g_tapw + ((size_t)k * PP + p) * 9;
#pragma unroll
        for (int dy = 0; dy < 3; dy++)
#pragma unroll
            for (int dx = 0; dx < 3; dx++) {
                toff[dy * 3 + dx] = base + (ry[dy] * WW + cx[dx]) * CC;
                tw[dy * 3 + dx] = wy[dy] * wx[dx];
            }
    } else if (bid == KK) {
        int t = tid;
        if (t < CC) {
            float s = gs[t] * rsqrtf(vs[t] + 1e-5f);
            g_sc_sem[t] = s;
            g_sh_sem[t] = bs[t] - ms[t] * s;
            float f = gf[t] * rsqrtf(vf[t] + 1e-5f);
            g_sc_fpn[t] = f;
            g_sh_fpn[t] = bfn[t] - mf[t] * f;
        }
        if (t < 64) {
            float a = ga[t] * rsqrtf(va[t] + 1e-5f);
            g_sc_aff[t] = a;
            g_sh_aff[t] = ba[t] - ma[t] * a;
        }
    } else if (bid < TRANS_BASE) {
        const int NW = 128 * 9 * 64;
        const int NA = 64 * PP;
        int total = 2 * NW + NA;
        int stride = 128 * 256;
        for (int d = (bid - KK - 1) * 256 + tid; d < total; d += stride) {
            if (d < NW) {
                int cp = d / 576, r = d % 576, tap = r / 64, oc = r % 64;
                g_wsemP[d] = pack_bf2(wsem[oc * (CC * 9) + (2 * cp) * 9 + tap],
                                      wsem[oc * (CC * 9) + (2 * cp + 1) * 9 + tap]);
            } else if (d < 2 * NW) {
                int e = d - NW;
                int cp = e / 576, r = e % 576, tap = r / 64, oc = r % 64;
                g_wfpnP[e] = pack_bf2(wfpn[oc * (CC * 9) + (2 * cp) * 9 + tap],
                                      wfpn[oc * (CC * 9) + (2 * cp + 1) * 9 + tap]);
            } else {
                int e = d - 2 * NW;
                int c = e / PP, n = e % PP;
                g_waffT[e] = waff[n * 64 + c];
            }
        }
    } else {
        __shared__ float tile[32][33];
        int bid2 = bid - TRANS_BASE;
        int b = bid2 / (392 * 8);
        int rem = bid2 % (392 * 8);
        int c0 = (rem / 392) * 32;
        int hw0 = (rem % 392) * 32;
        int tx = tid & 31, ty = tid >> 5;
        const float* src = sem + (size_t)b * CC * HWSZ;
        float* dst = g_semT + (size_t)b * HWSZ * CC;
#pragma unroll
        for (int yy = 0; yy < 32; yy += 8)
            tile[ty + yy][tx] = src[(size_t)(c0 + ty + yy) * HWSZ + hw0 + tx];
        __syncthreads();
#pragma unroll
        for (int yy = 0; yy < 32; yy += 8)
            dst[(size_t)(hw0 + ty + yy) * CC + c0 + tx] = tile[tx][ty + yy];
    }
}

// ---------------- ROI align gather (9-tap) ----------------
__global__ __launch_bounds__(256)
void k_roialign() {
    __shared__ int soff[28 * 9];
    __shared__ float sw[28 * 9];
    int k = blockIdx.y;
    int p0 = blockIdx.x * 28;
    int tid = threadIdx.x;
    for (int i = tid; i < 28 * 9; i += 256) {
        soff[i] = g_tapoff[((size_t)k * PP + p0) * 9 + i];
        sw[i] = g_tapw[((size_t)k * PP + p0) * 9 + i];
    }
    __syncthreads();
    int c = tid;
    for (int pp = 0; pp < 28; pp++) {
        float acc = 0.f;
#pragma unroll
        for (int t = 0; t < 9; t++)
            acc += sw[pp * 9 + t] * __ldg(&g_semT[soff[pp * 9 + t] + c]);
        g_roisem[((size_t)k * PP + p0 + pp) * CC + c] = acc;
    }
}

// ---------------- bf16 conv (R13 proven: cp.async staging) ----------------
__global__ __launch_bounds__(256, 2)
void k_conv_mma(const float* __restrict__ roi_feature,
                const float* __restrict__ bias_sem, const float* __restrict__ bias_fpn) {
    extern __shared__ float dyn[];
    unsigned* act = (unsigned*)dyn;
    unsigned* Bw = act + ACT_WORDS;
    float* rawS = (float*)(act + ACT_WORDS + B_WORDS);
    float* rawF = rawS + RAWF;
    int k = blockIdx.x;
    int tid = threadIdx.x;
    int warp = tid >> 5;
    int lane = tid & 31;
    int g = lane >> 2;
    int t = lane & 3;
    int wrow = warp * 32;

    float acc[2][8][4];
#pragma unroll
    for (int mg = 0; mg < 2; mg++)
#pragma unroll
        for (int n8 = 0; n8 < 8; n8++)
#pragma unroll
            for (int q = 0; q < 4; q++) acc[mg][n8][q] = 0.f;

    const float* rfk = roi_feature + (size_t)k * CC * PP;
    const float* rsk = g_roisem + (size_t)k * PP * CC;

    for (int i = tid; i < ACT_WORDS; i += 256) act[i] = 0u;

    for (int i = tid; i < PP * 8; i += 256) {
        int p = i >> 3, seg = i & 7;
        cp_async16(rawS + p * 32 + seg * 4, rsk + (size_t)p * CC + seg * 4);
    }
    for (int i = tid; i < 32 * 49; i += 256) {
        int row = i / 49, seg = i % 49;
        cp_async16(rawF + row * PP + seg * 4, rfk + (size_t)row * PP + seg * 4);
    }
    asm volatile("cp.async.commit_group;");
    asm volatile("cp.async.wait_group 0;");
    __syncthreads();
    for (int i = tid; i < PP * 16; i += 256) {
        int p = i >> 4, cp = i & 15;
        int c = 2 * cp;
        float v0 = fmaxf(rawS[p * 32 + c] * g_sc_sem[c] + g_sh_sem[c], 0.f);
        float v1 = fmaxf(rawS[p * 32 + c + 1] * g_sc_sem[c + 1] + g_sh_sem[c + 1], 0.f);
        act[cp * ACT_STRW + GUARD + (p / OSZ) * 16 + (p % OSZ)] = pack_bf2(v0, v1);
    }
    for (int i = tid; i < 16 * PP; i += 256) {
        int cp = i / PP, p = i % PP;
        int c = 2 * cp;
        float v0 = fmaxf(rawF[(2 * cp) * PP + p] * g_sc_fpn[c] + g_sh_fpn[c], 0.f);
        float v1 = fmaxf(rawF[(2 * cp + 1) * PP + p] * g_sc_fpn[c + 1] + g_sh_fpn[c + 1], 0.f);
        act[(16 + cp) * ACT_STRW + GUARD + (p / OSZ) * 16 + (p % OSZ)] = pack_bf2(v0, v1);
    }

    for (int chunk = 0; chunk < 8; chunk++) {
        int ic0 = chunk * 32;
        int icp0 = ic0 >> 1;
#pragma unroll
        for (int j = 0; j < 4; j++) {
            int id2 = tid + j * 256;
            int cp = id2 >> 6, oc = id2 & 63;
            Bw[cp * BWSTR + oc] = g_wsemP[(size_t)(icp0 + cp) * 576 + 0 * 64 + oc];
        }
        if (chunk < 7) {
            int nic0 = ic0 + 32;
            for (int i = tid; i < PP * 8; i += 256) {
                int p = i >> 3, seg = i & 7;
                cp_async16(rawS + p * 32 + seg * 4, rsk + (size_t)p * CC + nic0 + seg * 4);
            }
            for (int i = tid; i < 32 * 49; i += 256) {
                int row = i / 49, seg = i % 49;
                cp_async16(rawF + row * PP + seg * 4, rfk + (size_t)(nic0 + row) * PP + seg * 4);
            }
            asm volatile("cp.async.commit_group;");
        }
        __syncthreads();

        int cur = 0;
        for (int idx = 0; idx < 18; idx++) {
            int br = idx / 9, tap = idx % 9;
            int off = (tap / 3 - 1) * 16 + (tap % 3 - 1);
            unsigned pw[4];
            if (idx < 17) {
                int nbr = (idx + 1) / 9, ntap = (idx + 1) % 9;
                const unsigned* wP = nbr ? g_wfpnP : g_wsemP;
#pragma unroll
                for (int j = 0; j < 4; j++) {
                    int id2 = tid + j * 256;
                    int cp = id2 >> 6, oc = id2 & 63;
                    pw[j] = wP[(size_t)(icp0 + cp) * 576 + ntap * 64 + oc];
                }
            }
            if (warp < 7) {
                const unsigned* actb = act + br * (16 * ACT_STRW);
                const unsigned* Bc = Bw + cur * (16 * BWSTR);
#pragma unroll
                for (int s = 0; s < 2; s++) {
                    unsigned bf[8][2];
#pragma unroll
                    for (int n8 = 0; n8 < 8; n8++) {
                        bf[n8][0] = Bc[(s * 8 + t) * BWSTR + n8 * 8 + g];
                        bf[n8][1] = Bc[(s * 8 + t + 4) * BWSTR + n8 * 8 + g];
                    }
                    unsigned af[2][4];
#pragma unroll
                    for (int mg = 0; mg < 2; mg++) {
                        int r0 = GUARD + wrow + mg * 16 + g + off;
                        const unsigned* a0 = actb + (s * 8 + t) * ACT_STRW + r0;
                        const unsigned* a1 = actb + (s * 8 + t + 4) * ACT_STRW + r0;
                        af[mg][0] = a0[0];
                        af[mg][1] = a0[8];
                        af[mg][2] = a1[0];
                        af[mg][3] = a1[8];
                    }
#pragma unroll
                    for (int mg = 0; mg < 2; mg++)
#pragma unroll
                        for (int n8 = 0; n8 < 8; n8++)
                            mma_bf16(acc[mg][n8], af[mg], bf[n8]);
                }
            }
            if (idx < 17) {
                unsigned* d = Bw + (cur ^ 1) * (16 * BWSTR);
#pragma unroll
                for (int j = 0; j < 4; j++) {
                    int id2 = tid + j * 256;
                    d[(id2 >> 6) * BWSTR + (id2 & 63)] = pw[j];
                }
            }
            __syncthreads();
            cur ^= 1;
        }

        if (chunk < 7) {
            int nic0 = ic0 + 32;
            asm volatile("cp.async.wait_group 0;");
            __syncthreads();
            for (int i = tid; i < PP * 16; i += 256) {
                int p = i >> 4, cp = i & 15;
                int c = nic0 + 2 * cp;
                float v0 = fmaxf(rawS[p * 32 + 2 * cp] * g_sc_sem[c] + g_sh_sem[c], 0.f);
                float v1 = fmaxf(rawS[p * 32 + 2 * cp + 1] * g_sc_sem[c + 1] + g_sh_sem[c + 1], 0.f);
                act[cp * ACT_STRW + GUARD + (p / OSZ) * 16 + (p % OSZ)] = pack_bf2(v0, v1);
            }
            for (int i = tid; i < 16 * PP; i += 256) {
                int cp = i / PP, p = i % PP;
                int c = nic0 + 2 * cp;
                float v0 = fmaxf(rawF[(2 * cp) * PP + p] * g_sc_fpn[c] + g_sh_fpn[c], 0.f);
                float v1 = fmaxf(rawF[(2 * cp + 1) * PP + p] * g_sc_fpn[c + 1] + g_sh_fpn[c + 1], 0.f);
                act[(16 + cp) * ACT_STRW + GUARD + (p / OSZ) * 16 + (p % OSZ)] = pack_bf2(v0, v1);
            }
        }
    }

    float* outsm = dyn;
#pragma unroll
    for (int og = 0; og < 2; og++) {
        __syncthreads();
        if (warp < 7) {
#pragma unroll
            for (int mg = 0; mg < 2; mg++) {
                int r0 = wrow + mg * 16 + g;
#pragma unroll
                for (int nn = 0; nn < 4; nn++) {
                    int n8 = og * 4 + nn;
                    int ocl = nn * 8 + 2 * t;
                    outsm[ocl * OUT2_STR + r0] = acc[mg][n8][0];
                    outsm[(ocl + 1) * OUT2_STR + r0] = acc[mg][n8][1];
                    outsm[ocl * OUT2_STR + r0 + 8] = acc[mg][n8][2];
                    outsm[(ocl + 1) * OUT2_STR + r0 + 8] = acc[mg][n8][3];
                }
            }
        }
        __syncthreads();
        for (int i = tid; i < 32 * PP; i += 256) {
            int ocl = i / PP, p = i % PP;
            int oc = og * 32 + ocl;
            float v = outsm[ocl * OUT2_STR + (p / OSZ) * 16 + (p % OSZ)];
            g_abuf[((size_t)k * 64 + oc) * PP + p] = v + __ldg(&bias_sem[oc]) + __ldg(&bias_fpn[oc]);
        }
    }
}

// ---------------- aff via tf32 mma: ONE block per ROI, N-chunks looped ----------------
__global__ __launch_bounds__(224)
void k_aff_mma(const float* __restrict__ aff_b) {
    extern __shared__ float dyn[];
    float* sA = dyn;                     // [64][AFF_ASTR]
    float* sW = dyn + 64 * AFF_ASTR;     // [64][AFF_WSTR]
    int k = blockIdx.x;
    int tid = threadIdx.x;
    int warp = tid >> 5;
    int lane = tid & 31;
    int g = lane >> 2;
    int t = lane & 3;
    int wrow = warp * 32;

    // stage Ar once (no divisions: loop c, thread = p)
    {
        int p = tid;
        bool inb = p < PP;
        const float* ab = g_abuf + (size_t)k * 64 * PP + p;
#pragma unroll 4
        for (int c = 0; c < 64; c++) {
            float v = 0.f;
            if (inb) v = fmaxf(ab[c * PP] * g_sc_aff[c] + g_sh_aff[c], 0.f);
            sA[c * AFF_ASTR + p] = cvt_tf32(v);
        }
    }

    float degacc[2][2] = {{0.f, 0.f}, {0.f, 0.f}};
    int nn_t = tid % 56;
    int cq = tid / 56;
    float* Ak = g_Abuf + (size_t)k * PP * PP;

    for (int nc = 0; nc < 4; nc++) {
        int n0 = nc * 56;
        for (int r = 0; r < 16; r++) {
            int c = cq + 4 * r;
            int n = n0 + nn_t;
            float v = (n < PP) ? g_waffT[c * PP + n] : 0.f;
            sW[c * AFF_WSTR + nn_t] = cvt_tf32(v);
        }
        __syncthreads();

        float acc[2][7][4];
#pragma unroll
        for (int mg = 0; mg < 2; mg++)
#pragma unroll
            for (int n8 = 0; n8 < 7; n8++)
#pragma unroll
                for (int q = 0; q < 4; q++) acc[mg][n8][q] = 0.f;

#pragma unroll
        for (int ks = 0; ks < 8; ks++) {
            unsigned bf[7][2];
#pragma unroll
            for (int n8 = 0; n8 < 7; n8++) {
                bf[n8][0] = __float_as_uint(sW[(ks * 8 + t) * AFF_WSTR + n8 * 8 + g]);
                bf[n8][1] = __float_as_uint(sW[(ks * 8 + t + 4) * AFF_WSTR + n8 * 8 + g]);
            }
            unsigned af[2][4];
#pragma unroll
            for (int mg = 0; mg < 2; mg++) {
                int r0 = wrow + mg * 16 + g;
                const float* a0 = sA + (ks * 8 + t) * AFF_ASTR + r0;
                const float* a1 = sA + (ks * 8 + t + 4) * AFF_ASTR + r0;
                af[mg][0] = __float_as_uint(a0[0]);
                af[mg][1] = __float_as_uint(a0[8]);
                af[mg][2] = __float_as_uint(a1[0]);
                af[mg][3] = __float_as_uint(a1[8]);
            }
#pragma unroll
            for (int mg = 0; mg < 2; mg++)
#pragma unroll
                for (int n8 = 0; n8 < 7; n8++)
                    mma_tf32(acc[mg][n8], af[mg], bf[n8]);
        }

#pragma unroll
        for (int mg = 0; mg < 2; mg++) {
#pragma unroll
            for (int half = 0; half < 2; half++) {
                int p = wrow + mg * 16 + g + half * 8;
                if (p < PP) {
                    float dpart = 0.f;
#pragma unroll
                    for (int n8 = 0; n8 < 7; n8++) {
#pragma unroll
                        for (int q = 0; q < 2; q++) {
                            int n = n0 + n8 * 8 + 2 * t + q;
                            if (n < PP) {
                                float v = acc[mg][n8][half * 2 + q] + __ldg(&aff_b[n]);
                                float s = 1.f / (1.f + expf(-v));
                                Ak[(size_t)n * PP + p] = s;
                                dpart += s;
                            }
                        }
                    }
                    degacc[mg][half] += dpart;
                }
            }
        }
        __syncthreads();
    }

    // reduce degacc across the 4 t-lanes sharing each p (lanes differ in bits 0-1)
#pragma unroll
    for (int mg = 0; mg < 2; mg++)
#pragma unroll
        for (int half = 0; half < 2; half++) {
            float d = degacc[mg][half];
            d += __shfl_xor_sync(0xffffffffu, d, 1);
            d += __shfl_xor_sync(0xffffffffu, d, 2);
            int p = wrow + mg * 16 + g + half * 8;
            if (p < PP && t == 0) g_deg[k * PP + p] = d;
        }
}

// ---------------- fused xw1 + agg1 + relu + (x1 @ w2) scaled ----------------
__global__ __launch_bounds__(224)
void k_gcn1f(const float* __restrict__ rf, const float* __restrict__ w1,
             const float* __restrict__ b1, const float* __restrict__ w2) {
    __shared__ __align__(16) float sW1[CC * 16];
    __shared__ __align__(16) float sXW[PP * 16];
    __shared__ __align__(16) float sW2[16 * CC];
    int k = blockIdx.x;
    int tid = threadIdx.x;
    for (int i = tid; i < CC * 16; i += 224) sW1[i] = w1[i];
    for (int i = tid; i < 16 * CC; i += 224) sW2[i] = w2[i];
    __syncthreads();

    {
        int i = tid;
        if (i < PP) {
            float acc[16];
#pragma unroll
            for (int f = 0; f < 16; f++) acc[f] = 0.f;
            const float* x = rf + (size_t)k * CC * PP;
            for (int c = 0; c < CC; c++) {
                float v = x[c * PP + i];
#pragma unroll
                for (int fg = 0; fg < 4; fg++) {
                    float4 w4 = *(const float4*)&sW1[c * 16 + fg * 4];
                    acc[fg * 4 + 0] += v * w4.x;
                    acc[fg * 4 + 1] += v * w4.y;
                    acc[fg * 4 + 2] += v * w4.z;
                    acc[fg * 4 + 3] += v * w4.w;
                }
            }
            float di = rsqrtf(g_deg[k * PP + i]);
#pragma unroll
            for (int f = 0; f < 16; f++) sXW[i * 16 + f] = di * acc[f];
        }
    }
    __syncthreads();

    int j = tid;
    if (j >= PP) return;
    float acc[16];
#pragma unroll
    for (int f = 0; f < 16; f++) acc[f] = 0.f;
    const float* A = g_Abuf + (size_t)k * PP * PP;
    for (int i = 0; i < PP; i++) {
        float a = A[i * PP + j];
#pragma unroll
        for (int fg = 0; fg < 4; fg++) {
            float4 xv = *(const float4*)&sXW[i * 16 + fg * 4];
            acc[fg * 4 + 0] += a * xv.x;
            acc[fg * 4 + 1] += a * xv.y;
            acc[fg * 4 + 2] += a * xv.z;
            acc[fg * 4 + 3] += a * xv.w;
        }
    }
    float dj = rsqrtf(g_deg[k * PP + j]);
    float x1[16];
#pragma unroll
    for (int f = 0; f < 16; f++) x1[f] = fmaxf(acc[f] * dj + b1[f], 0.f);
    float* o = g_xw2 + ((size_t)k * PP + j) * CC;
    for (int g = 0; g < 64; g++) {
        float4 s = make_float4(0.f, 0.f, 0.f, 0.f);
#pragma unroll
        for (int f = 0; f < 16; f++) {
            float4 w4 = *(const float4*)&sW2[f * CC + g * 4];
            s.x += x1[f] * w4.x;
            s.y += x1[f] * w4.y;
            s.z += x1[f] * w4.z;
            s.w += x1[f] * w4.w;
        }
        s.x *= dj; s.y *= dj; s.z *= dj; s.w *= dj;
        *(float4*)&o[g * 4] = s;
    }
}

// ---------------- agg2 via tf32 mma ----------------
__global__ __launch_bounds__(224)
void k_gcn2_mma(const float* __restrict__ b2, float* __restrict__ out) {
    __shared__ float sA[32 * G2_ASTR];
    __shared__ float sX[32 * G2_XSTR];
    int f0 = blockIdx.x * 64;
    int k = blockIdx.y;
    int tid = threadIdx.x;
    int warp = tid >> 5;
    int lane = tid & 31;
    int g = lane >> 2;
    int t = lane & 3;
    int wrow = warp * 32;

    float acc[2][8][4];
#pragma unroll
    for (int mg = 0; mg < 2; mg++)
#pragma unroll
        for (int n8 = 0; n8 < 8; n8++)
#pragma unroll
            for (int q = 0; q < 4; q++) acc[mg][n8][q] = 0.f;

    const float* A = g_Abuf + (size_t)k * PP * PP;
    const float* X2 = g_xw2 + (size_t)k * PP * CC;

    for (int i0 = 0; i0 < 224; i0 += 32) {
        __syncthreads();
        for (int ii = 0; ii < 32; ii++) {
            int i = i0 + ii;
            float v = (i < PP && tid < PP) ? A[(size_t)i * PP + tid] : 0.f;
            sA[ii * G2_ASTR + tid] = cvt_tf32(v);
        }
        for (int idx = tid; idx < 32 * 64; idx += 224) {
            int ii = idx >> 6, ff = idx & 63;
            int i = i0 + ii;
            float v = (i < PP) ? X2[(size_t)i * CC + f0 + ff] : 0.f;
            sX[ii * G2_XSTR + ff] = cvt_tf32(v);
        }
        __syncthreads();
#pragma unroll
        for (int ks = 0; ks < 4; ks++) {
            unsigned bf[8][2];
#pragma unroll
            for (int n8 = 0; n8 < 8; n8++) {
                bf[n8][0] = __float_as_uint(sX[(ks * 8 + t) * G2_XSTR + n8 * 8 + g]);
                bf[n8][1] = __float_as_uint(sX[(ks * 8 + t + 4) * G2_XSTR + n8 * 8 + g]);
            }
            unsigned af[2][4];
#pragma unroll
            for (int mg = 0; mg < 2; mg++) {
                int r0 = wrow + mg * 16 + g;
                const float* a0 = sA + (ks * 8 + t) * G2_ASTR + r0;
                const float* a1 = sA + (ks * 8 + t + 4) * G2_ASTR + r0;
                af[mg][0] = __float_as_uint(a0[0]);
                af[mg][1] = __float_as_uint(a0[8]);
                af[mg][2] = __float_as_uint(a1[0]);
                af[mg][3] = __float_as_uint(a1[8]);
            }
#pragma unroll
            for (int mg = 0; mg < 2; mg++)
#pragma unroll
                for (int n8 = 0; n8 < 8; n8++)
                    mma_tf32(acc[mg][n8], af[mg], bf[n8]);
        }
    }

#pragma unroll
    for (int mg = 0; mg < 2; mg++) {
#pragma unroll
        for (int half = 0; half < 2; half++) {
            int j = wrow + mg * 16 + g + half * 8;
            if (j < PP) {
                float dj = rsqrtf(g_deg[k * PP + j]);
                const float* rs = g_roisem + ((size_t)k * PP + j) * CC;
#pragma unroll
                for (int n8 = 0; n8 < 8; n8++) {
                    int f = f0 + n8 * 8 + 2 * t;
                    float v0 = acc[mg][n8][half * 2 + 0];
                    float v1 = acc[mg][n8][half * 2 + 1];
                    out[((size_t)k * CC + f) * PP + j] = rs[f] + dj * v0 + __ldg(&b2[f]);
                    out[((size_t)k * CC + f + 1) * PP + j] = rs[f + 1] + dj * v1 + __ldg(&b2[f + 1]);
                }
            }
        }
    }
}

// ---------------- launch ----------------
extern "C" void kernel_launch(void* const* d_in, const int* in_sizes, int n_in,
                              void* d_out, int out_size) {
    const float* roi_feature = (const float*)d_in[0];
    const float* semantic = (const float*)d_in[1];
    const float* boxes = (const float*)d_in[2];
    const float* bn_sem_g = (const float*)d_in[3];
    const float* bn_sem_b = (const float*)d_in[4];
    const float* bn_sem_m = (const float*)d_in[5];
    const float* bn_sem_v = (const float*)d_in[6];
    const float* conv_sem_w = (const float*)d_in[7];
    const float* conv_sem_b = (const float*)d_in[8];
    const float* bn_fpn_g = (const float*)d_in[9];
    const float* bn_fpn_b = (const float*)d_in[10];
    const float* bn_fpn_m = (const float*)d_in[11];
    const float* bn_fpn_v = (const float*)d_in[12];
    const float* conv_fpn_w = (const float*)d_in[13];
    const float* conv_fpn_b = (const float*)d_in[14];
    const float* bn_aff_g = (const float*)d_in[15];
    const float* bn_aff_b = (const float*)d_in[16];
    const float* bn_aff_m = (const float*)d_in[17];
    const float* bn_aff_v = (const float*)d_in[18];
    const float* conv_aff_w = (const float*)d_in[19];
    const float* conv_aff_b = (const float*)d_in[20];
    const float* gcn1_w = (const float*)d_in[21];
    const float* gcn1_b = (const float*)d_in[22];
    const float* gcn2_w = (const float*)d_in[23];
    const float* gcn2_b = (const float*)d_in[24];
    float* out = (float*)d_out;

    static int smem_set = 0;
    if (!smem_set) {
        cudaFuncSetAttribute(k_conv_mma, cudaFuncAttributeMaxDynamicSharedMemorySize, CONV_SMEM);
        cudaFuncSetAttribute(k_aff_mma, cudaFuncAttributeMaxDynamicSharedMemorySize, AFF_SMEM);
        smem_set = 1;
    }

    k_prep_trans<<<TRANS_BASE + 12544, 256>>>(boxes,
                                              bn_sem_g, bn_sem_b, bn_sem_m, bn_sem_v,
                                              bn_fpn_g, bn_fpn_b, bn_fpn_m, bn_fpn_v,
                                              bn_aff_g, bn_aff_b, bn_aff_m, bn_aff_v,
                                              conv_sem_w, conv_fpn_w, conv_aff_w, semantic);
    {
        dim3 g(7, KK);
        k_roialign<<<g, 256>>>();
    }
    k_conv_mma<<<KK, 256, CONV_SMEM>>>(roi_feature, conv_sem_b, conv_fpn_b);
    k_aff_mma<<<KK, 224, AFF_SMEM>>>(conv_aff_b);
    k_gcn1f<<<KK, 224>>>(roi_feature, gcn1_w, gcn1_b, gcn2_w);
    {
        dim3 g(4, KK);
        k_gcn2_mma<<<g, 224>>>(gcn2_b, out);
    }
}

// round 17
// speedup vs baseline: 1.4355x; 1.3085x over previous
#include <cuda_runtime.h>
#include <cuda_bf16.h>
#include <math.h>

#define KK 256
#define CC 256
#define PP 196
#define OSZ 14
#define HH 112
#define WW 112
#define BB 4
#define HWSZ 12544

// conv-mma geometry (bf16 + cp.async raw staging) — R13 proven
#define ACT_STRW 296
#define GUARD 17
#define BWSTR 72
#define ACT_WORDS (32 * ACT_STRW)
#define B_WORDS (2 * 16 * BWSTR)
#define RAWF 6272
#define CONV_SMEM ((ACT_WORDS + B_WORDS + 2 * RAWF) * 4)
#define OUT2_STR 233

// aff-mma geometry
#define AFF_ASTR 232
#define AFF_WSTR 72
#define AFF_SMEM ((64 * AFF_ASTR + 64 * AFF_WSTR) * 4)

// gcn fused geometry (floats)
#define GCN_W1 0
#define GCN_W2 4096
#define GCN_XW 8192
#define GCN_RS 11392
#define GCN_SMEM ((11392 + 224 * 33) * 4)   // 75136 B

// ---------------- scratch ----------------
__device__ float g_semT[BB * HWSZ * CC];
__device__ float g_roisem[KK * PP * CC];
__device__ float g_abuf[KK * 64 * PP];
__device__ float g_Abuf[KK * PP * PP];
__device__ float g_deg[KK * PP];
__device__ unsigned g_wsemP[128 * 9 * 64];
__device__ unsigned g_wfpnP[128 * 9 * 64];
__device__ float g_waffT[64 * PP];
__device__ int   g_tapoff[KK * PP * 9];
__device__ float g_tapw[KK * PP * 9];
__device__ float g_sc_sem[CC], g_sh_sem[CC];
__device__ float g_sc_fpn[CC], g_sh_fpn[CC];
__device__ float g_sc_aff[64], g_sh_aff[64];

__device__ __forceinline__ float cvt_tf32(float x) {
    unsigned r;
    asm("cvt.rna.tf32.f32 %0, %1;" : "=r"(r) : "f"(x));
    return __uint_as_float(r);
}

__device__ __forceinline__ unsigned pack_bf2(float a, float b) {
    __nv_bfloat162 h = __floats2bfloat162_rn(a, b);
    return *(unsigned*)&h;
}

__device__ __forceinline__ void cp_async16(float* smem_dst, const float* gsrc) {
    unsigned saddr = (unsigned)__cvta_generic_to_shared(smem_dst);
    asm volatile("cp.async.cg.shared.global [%0], [%1], 16;" :: "r"(saddr), "l"(gsrc));
}

__device__ __forceinline__ void mma_tf32(float* c, const unsigned* a, const unsigned* b) {
    asm volatile(
        "mma.sync.aligned.m16n8k8.row.col.f32.tf32.tf32.f32 "
        "{%0,%1,%2,%3}, {%4,%5,%6,%7}, {%8,%9}, {%0,%1,%2,%3};"
        : "+f"(c[0]), "+f"(c[1]), "+f"(c[2]), "+f"(c[3])
        : "r"(a[0]), "r"(a[1]), "r"(a[2]), "r"(a[3]), "r"(b[0]), "r"(b[1]));
}

__device__ __forceinline__ void mma_bf16(float* c, const unsigned* a, const unsigned* b) {
    asm volatile(
        "mma.sync.aligned.m16n8k16.row.col.f32.bf16.bf16.f32 "
        "{%0,%1,%2,%3}, {%4,%5,%6,%7}, {%8,%9}, {%0,%1,%2,%3};"
        : "+f"(c[0]), "+f"(c[1]), "+f"(c[2]), "+f"(c[3])
        : "r"(a[0]), "r"(a[1]), "r"(a[2]), "r"(a[3]), "r"(b[0]), "r"(b[1]));
}

// ---------------- merged prep + semantic transpose ----------------
#define TRANS_BASE (KK + 1 + 128)
__global__ void k_prep_trans(const float* __restrict__ boxes,
                             const float* gs, const float* bs, const float* ms, const float* vs,
                             const float* gf, const float* bfn, const float* mf, const float* vf,
                             const float* ga, const float* ba, const float* ma, const float* va,
                             const float* wsem, const float* wfpn, const float* waff,
                             const float* __restrict__ sem) {
    int bid = blockIdx.x;
    int tid = threadIdx.x;
    if (bid < KK) {
        int k = bid;
        int p = tid;
        if (p >= PP) return;
        int bidx = (int)boxes[k * 5 + 0];
        float x1 = boxes[k * 5 + 1], y1 = boxes[k * 5 + 2];
        int oy = p / OSZ, ox = p % OSZ;
        int base = bidx * HWSZ * CC;
        int r0 = (int)floorf(y1 + 0.5f);
        int c0 = (int)floorf(x1 + 0.5f);
        float ly = (y1 + 0.5f) - (float)r0;
        float lx = (x1 + 0.5f) - (float)c0;
        float wy[3] = {0.5f * (1.f - ly), 0.5f, 0.5f * ly};
        float wx[3] = {0.5f * (1.f - lx), 0.5f, 0.5f * lx};
        int ry[3], cx[3];
#pragma unroll
        for (int d = 0; d < 3; d++) {
            ry[d] = min(r0 + 2 * oy + d, HH - 1);
            cx[d] = min(c0 + 2 * ox + d, WW - 1);
        }
        int* toff = g_tapoff + ((size_t)k * PP + p) * 9;
        float* tw = g_tapw + ((size_t)k * PP + p) * 9;
#pragma unroll
        for (int dy = 0; dy < 3; dy++)
#pragma unroll
            for (int dx = 0; dx < 3; dx++) {
                toff[dy * 3 + dx] = base + (ry[dy] * WW + cx[dx]) * CC;
                tw[dy * 3 + dx] = wy[dy] * wx[dx];
            }
    } else if (bid == KK) {
        int t = tid;
        if (t < CC) {
            float s = gs[t] * rsqrtf(vs[t] + 1e-5f);
            g_sc_sem[t] = s;
            g_sh_sem[t] = bs[t] - ms[t] * s;
            float f = gf[t] * rsqrtf(vf[t] + 1e-5f);
            g_sc_fpn[t] = f;
            g_sh_fpn[t] = bfn[t] - mf[t] * f;
        }
        if (t < 64) {
            float a = ga[t] * rsqrtf(va[t] + 1e-5f);
            g_sc_aff[t] = a;
            g_sh_aff[t] = ba[t] - ma[t] * a;
        }
    } else if (bid < TRANS_BASE) {
        const int NW = 128 * 9 * 64;
        const int NA = 64 * PP;
        int total = 2 * NW + NA;
        int stride = 128 * 256;
        for (int d = (bid - KK - 1) * 256 + tid; d < total; d += stride) {
            if (d < NW) {
                int cp = d / 576, r = d % 576, tap = r / 64, oc = r % 64;
                g_wsemP[d] = pack_bf2(wsem[oc * (CC * 9) + (2 * cp) * 9 + tap],
                                      wsem[oc * (CC * 9) + (2 * cp + 1) * 9 + tap]);
            } else if (d < 2 * NW) {
                int e = d - NW;
                int cp = e / 576, r = e % 576, tap = r / 64, oc = r % 64;
                g_wfpnP[e] = pack_bf2(wfpn[oc * (CC * 9) + (2 * cp) * 9 + tap],
                                      wfpn[oc * (CC * 9) + (2 * cp + 1) * 9 + tap]);
            } else {
                int e = d - 2 * NW;
                int c = e / PP, n = e % PP;
                g_waffT[e] = waff[n * 64 + c];
            }
        }
    } else {
        __shared__ float tile[32][33];
        int bid2 = bid - TRANS_BASE;
        int b = bid2 / (392 * 8);
        int rem = bid2 % (392 * 8);
        int c0 = (rem / 392) * 32;
        int hw0 = (rem % 392) * 32;
        int tx = tid & 31, ty = tid >> 5;
        const float* src = sem + (size_t)b * CC * HWSZ;
        float* dst = g_semT + (size_t)b * HWSZ * CC;
#pragma unroll
        for (int yy = 0; yy < 32; yy += 8)
            tile[ty + yy][tx] = src[(size_t)(c0 + ty + yy) * HWSZ + hw0 + tx];
        __syncthreads();
#pragma unroll
        for (int yy = 0; yy < 32; yy += 8)
            dst[(size_t)(hw0 + ty + yy) * CC + c0 + tx] = tile[tx][ty + yy];
    }
}

// ---------------- ROI align gather (9-tap) ----------------
__global__ __launch_bounds__(256)
void k_roialign() {
    __shared__ int soff[28 * 9];
    __shared__ float sw[28 * 9];
    int k = blockIdx.y;
    int p0 = blockIdx.x * 28;
    int tid = threadIdx.x;
    for (int i = tid; i < 28 * 9; i += 256) {
        soff[i] = g_tapoff[((size_t)k * PP + p0) * 9 + i];
        sw[i] = g_tapw[((size_t)k * PP + p0) * 9 + i];
    }
    __syncthreads();
    int c = tid;
    for (int pp = 0; pp < 28; pp++) {
        float acc = 0.f;
#pragma unroll
        for (int t = 0; t < 9; t++)
            acc += sw[pp * 9 + t] * __ldg(&g_semT[soff[pp * 9 + t] + c]);
        g_roisem[((size_t)k * PP + p0 + pp) * CC + c] = acc;
    }
}

// ---------------- bf16 conv (R13 proven: cp.async staging) ----------------
__global__ __launch_bounds__(256, 2)
void k_conv_mma(const float* __restrict__ roi_feature,
                const float* __restrict__ bias_sem, const float* __restrict__ bias_fpn) {
    extern __shared__ float dyn[];
    unsigned* act = (unsigned*)dyn;
    unsigned* Bw = act + ACT_WORDS;
    float* rawS = (float*)(act + ACT_WORDS + B_WORDS);
    float* rawF = rawS + RAWF;
    int k = blockIdx.x;
    int tid = threadIdx.x;
    int warp = tid >> 5;
    int lane = tid & 31;
    int g = lane >> 2;
    int t = lane & 3;
    int wrow = warp * 32;

    float acc[2][8][4];
#pragma unroll
    for (int mg = 0; mg < 2; mg++)
#pragma unroll
        for (int n8 = 0; n8 < 8; n8++)
#pragma unroll
            for (int q = 0; q < 4; q++) acc[mg][n8][q] = 0.f;

    const float* rfk = roi_feature + (size_t)k * CC * PP;
    const float* rsk = g_roisem + (size_t)k * PP * CC;

    for (int i = tid; i < ACT_WORDS; i += 256) act[i] = 0u;

    for (int i = tid; i < PP * 8; i += 256) {
        int p = i >> 3, seg = i & 7;
        cp_async16(rawS + p * 32 + seg * 4, rsk + (size_t)p * CC + seg * 4);
    }
    for (int i = tid; i < 32 * 49; i += 256) {
        int row = i / 49, seg = i % 49;
        cp_async16(rawF + row * PP + seg * 4, rfk + (size_t)row * PP + seg * 4);
    }
    asm volatile("cp.async.commit_group;");
    asm volatile("cp.async.wait_group 0;");
    __syncthreads();
    for (int i = tid; i < PP * 16; i += 256) {
        int p = i >> 4, cp = i & 15;
        int c = 2 * cp;
        float v0 = fmaxf(rawS[p * 32 + c] * g_sc_sem[c] + g_sh_sem[c], 0.f);
        float v1 = fmaxf(rawS[p * 32 + c + 1] * g_sc_sem[c + 1] + g_sh_sem[c + 1], 0.f);
        act[cp * ACT_STRW + GUARD + (p / OSZ) * 16 + (p % OSZ)] = pack_bf2(v0, v1);
    }
    for (int i = tid; i < 16 * PP; i += 256) {
        int cp = i / PP, p = i % PP;
        int c = 2 * cp;
        float v0 = fmaxf(rawF[(2 * cp) * PP + p] * g_sc_fpn[c] + g_sh_fpn[c], 0.f);
        float v1 = fmaxf(rawF[(2 * cp + 1) * PP + p] * g_sc_fpn[c + 1] + g_sh_fpn[c + 1], 0.f);
        act[(16 + cp) * ACT_STRW + GUARD + (p / OSZ) * 16 + (p % OSZ)] = pack_bf2(v0, v1);
    }

    for (int chunk = 0; chunk < 8; chunk++) {
        int ic0 = chunk * 32;
        int icp0 = ic0 >> 1;
#pragma unroll
        for (int j = 0; j < 4; j++) {
            int id2 = tid + j * 256;
            int cp = id2 >> 6, oc = id2 & 63;
            Bw[cp * BWSTR + oc] = g_wsemP[(size_t)(icp0 + cp) * 576 + 0 * 64 + oc];
        }
        if (chunk < 7) {
            int nic0 = ic0 + 32;
            for (int i = tid; i < PP * 8; i += 256) {
                int p = i >> 3, seg = i & 7;
                cp_async16(rawS + p * 32 + seg * 4, rsk + (size_t)p * CC + nic0 + seg * 4);
            }
            for (int i = tid; i < 32 * 49; i += 256) {
                int row = i / 49, seg = i % 49;
                cp_async16(rawF + row * PP + seg * 4, rfk + (size_t)(nic0 + row) * PP + seg * 4);
            }
            asm volatile("cp.async.commit_group;");
        }
        __syncthreads();

        int cur = 0;
        for (int idx = 0; idx < 18; idx++) {
            int br = idx / 9, tap = idx % 9;
            int off = (tap / 3 - 1) * 16 + (tap % 3 - 1);
            unsigned pw[4];
            if (idx < 17) {
                int nbr = (idx + 1) / 9, ntap = (idx + 1) % 9;
                const unsigned* wP = nbr ? g_wfpnP : g_wsemP;
#pragma unroll
                for (int j = 0; j < 4; j++) {
                    int id2 = tid + j * 256;
                    int cp = id2 >> 6, oc = id2 & 63;
                    pw[j] = wP[(size_t)(icp0 + cp) * 576 + ntap * 64 + oc];
                }
            }
            if (warp < 7) {
                const unsigned* actb = act + br * (16 * ACT_STRW);
                const unsigned* Bc = Bw + cur * (16 * BWSTR);
#pragma unroll
                for (int s = 0; s < 2; s++) {
                    unsigned bf[8][2];
#pragma unroll
                    for (int n8 = 0; n8 < 8; n8++) {
                        bf[n8][0] = Bc[(s * 8 + t) * BWSTR + n8 * 8 + g];
                        bf[n8][1] = Bc[(s * 8 + t + 4) * BWSTR + n8 * 8 + g];
                    }
                    unsigned af[2][4];
#pragma unroll
                    for (int mg = 0; mg < 2; mg++) {
                        int r0 = GUARD + wrow + mg * 16 + g + off;
                        const unsigned* a0 = actb + (s * 8 + t) * ACT_STRW + r0;
                        const unsigned* a1 = actb + (s * 8 + t + 4) * ACT_STRW + r0;
                        af[mg][0] = a0[0];
                        af[mg][1] = a0[8];
                        af[mg][2] = a1[0];
                        af[mg][3] = a1[8];
                    }
#pragma unroll
                    for (int mg = 0; mg < 2; mg++)
#pragma unroll
                        for (int n8 = 0; n8 < 8; n8++)
                            mma_bf16(acc[mg][n8], af[mg], bf[n8]);
                }
            }
            if (idx < 17) {
                unsigned* d = Bw + (cur ^ 1) * (16 * BWSTR);
#pragma unroll
                for (int j = 0; j < 4; j++) {
                    int id2 = tid + j * 256;
                    d[(id2 >> 6) * BWSTR + (id2 & 63)] = pw[j];
                }
            }
            __syncthreads();
            cur ^= 1;
        }

        if (chunk < 7) {
            int nic0 = ic0 + 32;
            asm volatile("cp.async.wait_group 0;");
            __syncthreads();
            for (int i = tid; i < PP * 16; i += 256) {
                int p = i >> 4, cp = i & 15;
                int c = nic0 + 2 * cp;
                float v0 = fmaxf(rawS[p * 32 + 2 * cp] * g_sc_sem[c] + g_sh_sem[c], 0.f);
                float v1 = fmaxf(rawS[p * 32 + 2 * cp + 1] * g_sc_sem[c + 1] + g_sh_sem[c + 1], 0.f);
                act[cp * ACT_STRW + GUARD + (p / OSZ) * 16 + (p % OSZ)] = pack_bf2(v0, v1);
            }
            for (int i = tid; i < 16 * PP; i += 256) {
                int cp = i / PP, p = i % PP;
                int c = nic0 + 2 * cp;
                float v0 = fmaxf(rawF[(2 * cp) * PP + p] * g_sc_fpn[c] + g_sh_fpn[c], 0.f);
                float v1 = fmaxf(rawF[(2 * cp + 1) * PP + p] * g_sc_fpn[c + 1] + g_sh_fpn[c + 1], 0.f);
                act[(16 + cp) * ACT_STRW + GUARD + (p / OSZ) * 16 + (p % OSZ)] = pack_bf2(v0, v1);
            }
        }
    }

    float* outsm = dyn;
#pragma unroll
    for (int og = 0; og < 2; og++) {
        __syncthreads();
        if (warp < 7) {
#pragma unroll
            for (int mg = 0; mg < 2; mg++) {
                int r0 = wrow + mg * 16 + g;
#pragma unroll
                for (int nn = 0; nn < 4; nn++) {
                    int n8 = og * 4 + nn;
                    int ocl = nn * 8 + 2 * t;
                    outsm[ocl * OUT2_STR + r0] = acc[mg][n8][0];
                    outsm[(ocl + 1) * OUT2_STR + r0] = acc[mg][n8][1];
                    outsm[ocl * OUT2_STR + r0 + 8] = acc[mg][n8][2];
                    outsm[(ocl + 1) * OUT2_STR + r0 + 8] = acc[mg][n8][3];
                }
            }
        }
        __syncthreads();
        for (int i = tid; i < 32 * PP; i += 256) {
            int ocl = i / PP, p = i % PP;
            int oc = og * 32 + ocl;
            float v = outsm[ocl * OUT2_STR + (p / OSZ) * 16 + (p % OSZ)];
            g_abuf[((size_t)k * 64 + oc) * PP + p] = v + __ldg(&bias_sem[oc]) + __ldg(&bias_fpn[oc]);
        }
    }
}

// ---------------- aff via tf32 mma: one block per ROI (R16 proven) ----------------
__global__ __launch_bounds__(224)
void k_aff_mma(const float* __restrict__ aff_b) {
    extern __shared__ float dyn[];
    float* sA = dyn;
    float* sW = dyn + 64 * AFF_ASTR;
    int k = blockIdx.x;
    int tid = threadIdx.x;
    int warp = tid >> 5;
    int lane = tid & 31;
    int g = lane >> 2;
    int t = lane & 3;
    int wrow = warp * 32;

    {
        int p = tid;
        bool inb = p < PP;
        const float* ab = g_abuf + (size_t)k * 64 * PP + p;
#pragma unroll 4
        for (int c = 0; c < 64; c++) {
            float v = 0.f;
            if (inb) v = fmaxf(ab[c * PP] * g_sc_aff[c] + g_sh_aff[c], 0.f);
            sA[c * AFF_ASTR + p] = cvt_tf32(v);
        }
    }

    float degacc[2][2] = {{0.f, 0.f}, {0.f, 0.f}};
    int nn_t = tid % 56;
    int cq = tid / 56;
    float* Ak = g_Abuf + (size_t)k * PP * PP;

    for (int nc = 0; nc < 4; nc++) {
        int n0 = nc * 56;
        for (int r = 0; r < 16; r++) {
            int c = cq + 4 * r;
            int n = n0 + nn_t;
            float v = (n < PP) ? g_waffT[c * PP + n] : 0.f;
            sW[c * AFF_WSTR + nn_t] = cvt_tf32(v);
        }
        __syncthreads();

        float acc[2][7][4];
#pragma unroll
        for (int mg = 0; mg < 2; mg++)
#pragma unroll
            for (int n8 = 0; n8 < 7; n8++)
#pragma unroll
                for (int q = 0; q < 4; q++) acc[mg][n8][q] = 0.f;

#pragma unroll
        for (int ks = 0; ks < 8; ks++) {
            unsigned bf[7][2];
#pragma unroll
            for (int n8 = 0; n8 < 7; n8++) {
                bf[n8][0] = __float_as_uint(sW[(ks * 8 + t) * AFF_WSTR + n8 * 8 + g]);
                bf[n8][1] = __float_as_uint(sW[(ks * 8 + t + 4) * AFF_WSTR + n8 * 8 + g]);
            }
            unsigned af[2][4];
#pragma unroll
            for (int mg = 0; mg < 2; mg++) {
                int r0 = wrow + mg * 16 + g;
                const float* a0 = sA + (ks * 8 + t) * AFF_ASTR + r0;
                const float* a1 = sA + (ks * 8 + t + 4) * AFF_ASTR + r0;
                af[mg][0] = __float_as_uint(a0[0]);
                af[mg][1] = __float_as_uint(a0[8]);
                af[mg][2] = __float_as_uint(a1[0]);
                af[mg][3] = __float_as_uint(a1[8]);
            }
#pragma unroll
            for (int mg = 0; mg < 2; mg++)
#pragma unroll
                for (int n8 = 0; n8 < 7; n8++)
                    mma_tf32(acc[mg][n8], af[mg], bf[n8]);
        }

#pragma unroll
        for (int mg = 0; mg < 2; mg++) {
#pragma unroll
            for (int half = 0; half < 2; half++) {
                int p = wrow + mg * 16 + g + half * 8;
                if (p < PP) {
                    float dpart = 0.f;
#pragma unroll
                    for (int n8 = 0; n8 < 7; n8++) {
#pragma unroll
                        for (int q = 0; q < 2; q++) {
                            int n = n0 + n8 * 8 + 2 * t + q;
                            if (n < PP) {
                                float v = acc[mg][n8][half * 2 + q] + __ldg(&aff_b[n]);
                                float s = 1.f / (1.f + expf(-v));
                                Ak[(size_t)n * PP + p] = s;
                                dpart += s;
                            }
                        }
                    }
                    degacc[mg][half] += dpart;
                }
            }
        }
        __syncthreads();
    }

#pragma unroll
    for (int mg = 0; mg < 2; mg++)
#pragma unroll
        for (int half = 0; half < 2; half++) {
            float d = degacc[mg][half];
            d += __shfl_xor_sync(0xffffffffu, d, 1);
            d += __shfl_xor_sync(0xffffffffu, d, 2);
            int p = wrow + mg * 16 + g + half * 8;
            if (p < PP && t == 0) g_deg[k * PP + p] = d;
        }
}

// ---------------- fused GCN: xw1 -> agg1 -> z -> agg2 -> @w2 + roi_sem -> out ----------------
// Key identity: emb_j = dis_j * (sum_i A[i][j] * z_i) @ w2 + b2, z_i = dis_i * x1_i.
__global__ __launch_bounds__(224)
void k_gcn(const float* __restrict__ rf, const float* __restrict__ w1,
           const float* __restrict__ b1, const float* __restrict__ w2,
           const float* __restrict__ b2, float* __restrict__ out) {
    extern __shared__ float dyn[];
    float* sW1 = dyn + GCN_W1;     // [256][16]
    float* sW2 = dyn + GCN_W2;     // [16][256]
    float* sXW = dyn + GCN_XW;     // [196][16] xw1s, later z
    float* srs = dyn + GCN_RS;     // [224][33] roi_sem staging
    int k = blockIdx.x;
    int tid = threadIdx.x;
    for (int i = tid; i < CC * 16; i += 224) sW1[i] = w1[i];
    for (int i = tid; i < 16 * CC; i += 224) sW2[i] = w2[i];
    __syncthreads();

    int j = tid;
    bool inb = j < PP;
    const float* A = g_Abuf + (size_t)k * PP * PP;
    float dj = inb ? rsqrtf(g_deg[k * PP + j]) : 0.f;

    // phase 1: sXW[i][f] = dis_i * (X @ w1)[i][f]
    if (inb) {
        float acc[16];
#pragma unroll
        for (int f = 0; f < 16; f++) acc[f] = 0.f;
        const float* x = rf + (size_t)k * CC * PP;
        for (int c = 0; c < CC; c++) {
            float v = x[c * PP + j];
#pragma unroll
            for (int fg = 0; fg < 4; fg++) {
                float4 w4 = *(const float4*)&sW1[c * 16 + fg * 4];
                acc[fg * 4 + 0] += v * w4.x;
                acc[fg * 4 + 1] += v * w4.y;
                acc[fg * 4 + 2] += v * w4.z;
                acc[fg * 4 + 3] += v * w4.w;
            }
        }
#pragma unroll
        for (int f = 0; f < 16; f++) sXW[j * 16 + f] = dj * acc[f];
    }
    __syncthreads();

    // phase 2: agg1 + relu -> z_j = dj * x1_j (in registers)
    float z[16];
    {
        float acc[16];
#pragma unroll
        for (int f = 0; f < 16; f++) acc[f] = 0.f;
        if (inb) {
            for (int i = 0; i < PP; i++) {
                float a = A[i * PP + j];
#pragma unroll
                for (int fg = 0; fg < 4; fg++) {
                    float4 xv = *(const float4*)&sXW[i * 16 + fg * 4];
                    acc[fg * 4 + 0] += a * xv.x;
                    acc[fg * 4 + 1] += a * xv.y;
                    acc[fg * 4 + 2] += a * xv.z;
                    acc[fg * 4 + 3] += a * xv.w;
                }
            }
        }
#pragma unroll
        for (int f = 0; f < 16; f++)
            z[f] = dj * fmaxf(acc[f] * dj + __ldg(&b1[f]), 0.f);
    }
    __syncthreads();   // all phase-2 reads of sXW done
    if (inb) {
#pragma unroll
        for (int f = 0; f < 16; f++) sXW[j * 16 + f] = z[f];
    }
    __syncthreads();

    // phase 3: Y_j = sum_i A[i][j] * z_i
    float Y[16];
#pragma unroll
    for (int f = 0; f < 16; f++) Y[f] = 0.f;
    if (inb) {
        for (int i = 0; i < PP; i++) {
            float a = A[i * PP + j];
#pragma unroll
            for (int fg = 0; fg < 4; fg++) {
                float4 xv = *(const float4*)&sXW[i * 16 + fg * 4];
                Y[fg * 4 + 0] += a * xv.x;
                Y[fg * 4 + 1] += a * xv.y;
                Y[fg * 4 + 2] += a * xv.z;
                Y[fg * 4 + 3] += a * xv.w;
            }
        }
    }

    // phase 4: out[k][f][j] = roi_sem[k][j][f] + dj * (Y @ w2)[f] + b2[f], 32-f chunks
    const float* rsk = g_roisem + (size_t)k * PP * CC;
    for (int fc = 0; fc < 8; fc++) {
        int f0 = fc * 32;
        __syncthreads();
        for (int idx = tid; idx < 224 * 32; idx += 224) {
            int p = idx >> 5, fl = idx & 31;
            srs[p * 33 + fl] = (p < PP) ? rsk[(size_t)p * CC + f0 + fl] : 0.f;
        }
        __syncthreads();
        if (inb) {
#pragma unroll 4
            for (int fl = 0; fl < 32; fl++) {
                int f = f0 + fl;
                float s = 0.f;
#pragma unroll
                for (int f16 = 0; f16 < 16; f16++)
                    s += Y[f16] * sW2[f16 * CC + f];
                out[((size_t)k * CC + f) * PP + j] = srs[j * 33 + fl] + dj * s + __ldg(&b2[f]);
            }
        }
    }
}

// ---------------- launch ----------------
extern "C" void kernel_launch(void* const* d_in, const int* in_sizes, int n_in,
                              void* d_out, int out_size) {
    const float* roi_feature = (const float*)d_in[0];
    const float* semantic = (const float*)d_in[1];
    const float* boxes = (const float*)d_in[2];
    const float* bn_sem_g = (const float*)d_in[3];
    const float* bn_sem_b = (const float*)d_in[4];
    const float* bn_sem_m = (const float*)d_in[5];
    const float* bn_sem_v = (const float*)d_in[6];
    const float* conv_sem_w = (const float*)d_in[7];
    const float* conv_sem_b = (const float*)d_in[8];
    const float* bn_fpn_g = (const float*)d_in[9];
    const float* bn_fpn_b = (const float*)d_in[10];
    const float* bn_fpn_m = (const float*)d_in[11];
    const float* bn_fpn_v = (const float*)d_in[12];
    const float* conv_fpn_w = (const float*)d_in[13];
    const float* conv_fpn_b = (const float*)d_in[14];
    const float* bn_aff_g = (const float*)d_in[15];
    const float* bn_aff_b = (const float*)d_in[16];
    const float* bn_aff_m = (const float*)d_in[17];
    const float* bn_aff_v = (const float*)d_in[18];
    const float* conv_aff_w = (const float*)d_in[19];
    const float* conv_aff_b = (const float*)d_in[20];
    const float* gcn1_w = (const float*)d_in[21];
    const float* gcn1_b = (const float*)d_in[22];
    const float* gcn2_w = (const float*)d_in[23];
    const float* gcn2_b = (const float*)d_in[24];
    float* out = (float*)d_out;

    static int smem_set = 0;
    if (!smem_set) {
        cudaFuncSetAttribute(k_conv_mma, cudaFuncAttributeMaxDynamicSharedMemorySize, CONV_SMEM);
        cudaFuncSetAttribute(k_aff_mma, cudaFuncAttributeMaxDynamicSharedMemorySize, AFF_SMEM);
        cudaFuncSetAttribute(k_gcn, cudaFuncAttributeMaxDynamicSharedMemorySize, GCN_SMEM);
        smem_set = 1;
    }

    k_prep_trans<<<TRANS_BASE + 12544, 256>>>(boxes,
                                              bn_sem_g, bn_sem_b, bn_sem_m, bn_sem_v,
                                              bn_fpn_g, bn_fpn_b, bn_fpn_m, bn_fpn_v,
                                              bn_aff_g, bn_aff_b, bn_aff_m, bn_aff_v,
                                              conv_sem_w, conv_fpn_w, conv_aff_w, semantic);
    {
        dim3 g(7, KK);
        k_roialign<<<g, 256>>>();
    }
    k_conv_mma<<<KK, 256, CONV_SMEM>>>(roi_feature, conv_sem_b, conv_fpn_b);
    k_aff_mma<<<KK, 224, AFF_SMEM>>>(conv_aff_b);
    k_gcn<<<KK, 224, GCN_SMEM>>>(roi_feature, gcn1_w, gcn1_b, gcn2_w, gcn2_b, out);
}